// round 1
// baseline (speedup 1.0000x reference)
#include <cuda_runtime.h>
#include <cstdint>
#include <cstddef>

// Problem constants
#define PB 4
#define PS 2048
#define PD 2048
#define PH 16
#define PDK 128
#define PM (PB*PS)          // 8192 rows of the "token" matrix

// ---------------------------------------------------------------------------
// Scratch (device globals; no allocation allowed)
// ---------------------------------------------------------------------------
__device__ float g_q [PB*PH*PS*PDK];   // [B,H,S,DK]
__device__ float g_k [PB*PH*PS*PDK];
__device__ float g_v [PB*PH*PS*PDK];
__device__ float g_ao[PM*PD];          // attention output, [B,S,D]

// ---------------------------------------------------------------------------
// NT GEMM: C[m,n] = sum_k A[m,k] * W[n,k],  M=8192, N=2048, K=2048
// mode 0: RoPE epilogue + store to [B,H,S,DK]   (Q, K projections)
// mode 1: store to [B,H,S,DK]                    (V projection)
// mode 2: plain row-major store [M,N]            (output projection)
// BM=BN=128, BK=16, 256 threads, 8x8 microtile (cols split tx*4 / 64+tx*4)
// ---------------------------------------------------------------------------
__global__ __launch_bounds__(256, 2)
void gemm_nt(const float* __restrict__ A, const float* __restrict__ W,
             float* __restrict__ C, const float* __restrict__ cosp,
             const float* __restrict__ sinp, int mode)
{
    __shared__ float As[16][128];
    __shared__ float Bs[16][128];

    const int tid = threadIdx.x;
    const int tx = tid & 15, ty = tid >> 4;
    const int rowBlock = blockIdx.y * 128;
    const int colBlock = blockIdx.x * 128;

    // loader indices: 512 float4 per operand tile, 2 per thread
    const int ar0 = tid >> 2,        ap0 = tid & 3;
    const int ar1 = (tid + 256) >> 2, ap1 = (tid + 256) & 3;

    const float* Ap0 = A + (size_t)(rowBlock + ar0) * PD + ap0 * 4;
    const float* Ap1 = A + (size_t)(rowBlock + ar1) * PD + ap1 * 4;
    const float* Bp0 = W + (size_t)(colBlock + ar0) * PD + ap0 * 4;
    const float* Bp1 = W + (size_t)(colBlock + ar1) * PD + ap1 * 4;

    float acc[8][8];
#pragma unroll
    for (int i = 0; i < 8; ++i)
#pragma unroll
        for (int j = 0; j < 8; ++j) acc[i][j] = 0.0f;

    // prologue fetch of tile 0
    float4 a0 = *(const float4*)(Ap0);
    float4 a1 = *(const float4*)(Ap1);
    float4 b0 = *(const float4*)(Bp0);
    float4 b1 = *(const float4*)(Bp1);

    const int NT = PD / 16;   // 128 k-tiles
    for (int kt = 0; kt < NT; ++kt) {
        __syncthreads();   // previous tile's reads done
        As[ap0*4+0][ar0] = a0.x; As[ap0*4+1][ar0] = a0.y;
        As[ap0*4+2][ar0] = a0.z; As[ap0*4+3][ar0] = a0.w;
        As[ap1*4+0][ar1] = a1.x; As[ap1*4+1][ar1] = a1.y;
        As[ap1*4+2][ar1] = a1.z; As[ap1*4+3][ar1] = a1.w;
        Bs[ap0*4+0][ar0] = b0.x; Bs[ap0*4+1][ar0] = b0.y;
        Bs[ap0*4+2][ar0] = b0.z; Bs[ap0*4+3][ar0] = b0.w;
        Bs[ap1*4+0][ar1] = b1.x; Bs[ap1*4+1][ar1] = b1.y;
        Bs[ap1*4+2][ar1] = b1.z; Bs[ap1*4+3][ar1] = b1.w;
        __syncthreads();

        if (kt + 1 < NT) {   // prefetch next tile while computing
            a0 = *(const float4*)(Ap0 + (kt+1)*16);
            a1 = *(const float4*)(Ap1 + (kt+1)*16);
            b0 = *(const float4*)(Bp0 + (kt+1)*16);
            b1 = *(const float4*)(Bp1 + (kt+1)*16);
        }

#pragma unroll
        for (int k = 0; k < 16; ++k) {
            float4 av0 = *(const float4*)(&As[k][ty*8]);
            float4 av1 = *(const float4*)(&As[k][ty*8+4]);
            float4 bv0 = *(const float4*)(&Bs[k][tx*4]);
            float4 bv1 = *(const float4*)(&Bs[k][tx*4+64]);
            float ar[8] = {av0.x,av0.y,av0.z,av0.w,av1.x,av1.y,av1.z,av1.w};
            float br[8] = {bv0.x,bv0.y,bv0.z,bv0.w,bv1.x,bv1.y,bv1.z,bv1.w};
#pragma unroll
            for (int i = 0; i < 8; ++i)
#pragma unroll
                for (int j = 0; j < 8; ++j)
                    acc[i][j] = fmaf(ar[i], br[j], acc[i][j]);
        }
    }

    // ---------------- epilogue ----------------
#pragma unroll
    for (int i = 0; i < 8; ++i) {
        const int m = rowBlock + ty*8 + i;
        const int s = m & (PS - 1);
        const int b = m >> 11;
#pragma unroll
        for (int g = 0; g < 2; ++g) {
            const int n0 = colBlock + g*64 + tx*4;
            if (mode == 2) {
                float4 o;
                o.x = acc[i][g*4+0]; o.y = acc[i][g*4+1];
                o.z = acc[i][g*4+2]; o.w = acc[i][g*4+3];
                *(float4*)(C + (size_t)m*PD + n0) = o;
            } else {
                const int h  = n0 >> 7;
                const int d0 = n0 & 127;
                const size_t base = (((size_t)b*PH + h)*PS + s)*PDK + d0;
                if (mode == 1) {
                    float4 o;
                    o.x = acc[i][g*4+0]; o.y = acc[i][g*4+1];
                    o.z = acc[i][g*4+2]; o.w = acc[i][g*4+3];
                    *(float4*)(C + base) = o;
                } else {
                    float4 o;
#pragma unroll
                    for (int p = 0; p < 2; ++p) {
                        const int d  = d0 + p*2;
                        const float c  = cosp[s*64 + (d >> 1)];
                        const float sn = sinp[s*64 + (d >> 1)];
                        const float xe = acc[i][g*4 + p*2];
                        const float xo = acc[i][g*4 + p*2 + 1];
                        ((float*)&o)[p*2]   = xe*c - xo*sn;
                        ((float*)&o)[p*2+1] = xo*c + xe*sn;
                    }
                    *(float4*)(C + base) = o;
                }
            }
        }
    }
}

// ---------------------------------------------------------------------------
// Flash attention, fp32, causal. One CTA = (bh, 64-row query block).
// Q,K stored k-major-transposed in smem -> conflict-free, FFMA-bound S phase.
// Per-thread: 4 query rows (ty*4+i), S cols tx*4+j, O cols tx*4 / 64+tx*4.
// Row stats reduced with shfl over the 16 tx lanes.
// ---------------------------------------------------------------------------
#define FLASH_SMEM ((3*128*64 + 64*64) * 4)   // 114688 bytes

__global__ __launch_bounds__(256, 2)
void flash_attn(const float* __restrict__ gq, const float* __restrict__ gk,
                const float* __restrict__ gv, float* __restrict__ gout)
{
    extern __shared__ float smf[];
    float* Qt = smf;                 // [128][64]  (k-major)
    float* Kt = smf + 128*64;        // [128][64]
    float* Vs = smf + 2*128*64;      // [64][128]  (row-major)
    float* Ps = smf + 3*128*64;      // [64][64]

    const int tid = threadIdx.x;
    const int tx = tid & 15, ty = tid >> 4;
    const int qb = blockIdx.x;
    const int bh = blockIdx.y;

    const float* Qg = gq + ((size_t)bh*PS + qb*64) * PDK;
    const float* Kg = gk + (size_t)bh*PS*PDK;
    const float* Vg = gv + (size_t)bh*PS*PDK;

    const float scale = 0.08838834764831845f;   // 1/sqrt(128)

    // load Q transposed + pre-scaled
#pragma unroll
    for (int it = 0; it < 8; ++it) {
        const int id = tid + it*256;
        const int r = id & 63, kq = id >> 6;
        float4 v = *(const float4*)(Qg + r*PDK + kq*4);
        Qt[(kq*4+0)*64 + r] = v.x * scale;
        Qt[(kq*4+1)*64 + r] = v.y * scale;
        Qt[(kq*4+2)*64 + r] = v.z * scale;
        Qt[(kq*4+3)*64 + r] = v.w * scale;
    }

    float accO[4][8];
    float m_i[4], l_i[4];
#pragma unroll
    for (int i = 0; i < 4; ++i) {
        m_i[i] = -1e30f; l_i[i] = 0.0f;
#pragma unroll
        for (int c = 0; c < 8; ++c) accO[i][c] = 0.0f;
    }
    __syncthreads();

    for (int kb = 0; kb <= qb; ++kb) {
        const float* Kgb = Kg + (size_t)kb*64*PDK;
        const float* Vgb = Vg + (size_t)kb*64*PDK;
#pragma unroll
        for (int it = 0; it < 8; ++it) {
            const int id = tid + it*256;
            const int r = id & 63, kq = id >> 6;
            float4 v = *(const float4*)(Kgb + r*PDK + kq*4);
            Kt[(kq*4+0)*64 + r] = v.x;
            Kt[(kq*4+1)*64 + r] = v.y;
            Kt[(kq*4+2)*64 + r] = v.z;
            Kt[(kq*4+3)*64 + r] = v.w;
        }
#pragma unroll
        for (int it = 0; it < 8; ++it) {
            const int id = tid + it*256;
            const int r = id >> 5, cq = id & 31;
            *(float4*)(Vs + r*PDK + cq*4) = *(const float4*)(Vgb + r*PDK + cq*4);
        }
        __syncthreads();

        // S = Q K^T (pre-scaled)
        float sc[4][4];
#pragma unroll
        for (int i = 0; i < 4; ++i)
#pragma unroll
            for (int j = 0; j < 4; ++j) sc[i][j] = 0.0f;

#pragma unroll 4
        for (int k = 0; k < 128; ++k) {
            float4 qv = *(const float4*)(Qt + k*64 + ty*4);
            float4 kv = *(const float4*)(Kt + k*64 + tx*4);
            float qa[4] = {qv.x, qv.y, qv.z, qv.w};
            float ka[4] = {kv.x, kv.y, kv.z, kv.w};
#pragma unroll
            for (int i = 0; i < 4; ++i)
#pragma unroll
                for (int j = 0; j < 4; ++j)
                    sc[i][j] = fmaf(qa[i], ka[j], sc[i][j]);
        }

        if (kb == qb) {   // causal mask on diagonal block
#pragma unroll
            for (int i = 0; i < 4; ++i)
#pragma unroll
                for (int j = 0; j < 4; ++j)
                    if (tx*4 + j > ty*4 + i) sc[i][j] = -1e30f;
        }

        // online softmax
#pragma unroll
        for (int i = 0; i < 4; ++i) {
            float bm = fmaxf(fmaxf(sc[i][0], sc[i][1]), fmaxf(sc[i][2], sc[i][3]));
#pragma unroll
            for (int off = 1; off < 16; off <<= 1)
                bm = fmaxf(bm, __shfl_xor_sync(0xffffffffu, bm, off));
            const float mn = fmaxf(m_i[i], bm);
            const float alpha = __expf(m_i[i] - mn);
            m_i[i] = mn;
            float p0 = __expf(sc[i][0] - mn);
            float p1 = __expf(sc[i][1] - mn);
            float p2 = __expf(sc[i][2] - mn);
            float p3 = __expf(sc[i][3] - mn);
            float4 pv = make_float4(p0, p1, p2, p3);
            *(float4*)(Ps + (ty*4+i)*64 + tx*4) = pv;
            float rs = p0 + p1 + p2 + p3;
#pragma unroll
            for (int off = 1; off < 16; off <<= 1)
                rs += __shfl_xor_sync(0xffffffffu, rs, off);
            l_i[i] = l_i[i]*alpha + rs;
#pragma unroll
            for (int c = 0; c < 8; ++c) accO[i][c] *= alpha;
        }
        __syncthreads();

        // O += P V
#pragma unroll 4
        for (int t = 0; t < 64; ++t) {
            float4 v0 = *(const float4*)(Vs + t*PDK + tx*4);
            float4 v1 = *(const float4*)(Vs + t*PDK + 64 + tx*4);
#pragma unroll
            for (int i = 0; i < 4; ++i) {
                const float p = Ps[(ty*4+i)*64 + t];
                accO[i][0] = fmaf(p, v0.x, accO[i][0]);
                accO[i][1] = fmaf(p, v0.y, accO[i][1]);
                accO[i][2] = fmaf(p, v0.z, accO[i][2]);
                accO[i][3] = fmaf(p, v0.w, accO[i][3]);
                accO[i][4] = fmaf(p, v1.x, accO[i][4]);
                accO[i][5] = fmaf(p, v1.y, accO[i][5]);
                accO[i][6] = fmaf(p, v1.z, accO[i][6]);
                accO[i][7] = fmaf(p, v1.w, accO[i][7]);
            }
        }
        __syncthreads();
    }

    // normalize + store to [B,S,D]
    const int b = bh >> 4, h = bh & 15;
#pragma unroll
    for (int i = 0; i < 4; ++i) {
        const float inv = 1.0f / l_i[i];
        const int sg = qb*64 + ty*4 + i;
        const size_t base = ((size_t)b*PS + sg)*PD + h*PDK;
        float4 o0 = make_float4(accO[i][0]*inv, accO[i][1]*inv,
                                accO[i][2]*inv, accO[i][3]*inv);
        float4 o1 = make_float4(accO[i][4]*inv, accO[i][5]*inv,
                                accO[i][6]*inv, accO[i][7]*inv);
        *(float4*)(gout + base + tx*4)      = o0;
        *(float4*)(gout + base + 64 + tx*4) = o1;
    }
}

// ---------------------------------------------------------------------------
extern "C" void kernel_launch(void* const* d_in, const int* in_sizes, int n_in,
                              void* d_out, int out_size)
{
    (void)in_sizes; (void)n_in; (void)out_size;
    const float* x  = (const float*)d_in[0];
    const float* Wq = (const float*)d_in[1];
    const float* Wk = (const float*)d_in[2];
    const float* Wv = (const float*)d_in[3];
    const float* Wo = (const float*)d_in[4];
    const float* cs = (const float*)d_in[5];
    const float* sn = (const float*)d_in[6];
    float* out = (float*)d_out;

    float *pq, *pk, *pv, *pao;
    cudaGetSymbolAddress((void**)&pq,  g_q);
    cudaGetSymbolAddress((void**)&pk,  g_k);
    cudaGetSymbolAddress((void**)&pv,  g_v);
    cudaGetSymbolAddress((void**)&pao, g_ao);
    cudaFuncSetAttribute(flash_attn, cudaFuncAttributeMaxDynamicSharedMemorySize,
                         FLASH_SMEM);

    dim3 tb(256);
    dim3 gb(PD/128, PM/128);        // (16, 64)
    gemm_nt<<<gb, tb>>>(x,  Wq, pq,  cs, sn, 0);
    gemm_nt<<<gb, tb>>>(x,  Wk, pk,  cs, sn, 0);
    gemm_nt<<<gb, tb>>>(x,  Wv, pv,  cs, sn, 1);

    dim3 fg(PS/64, PB*PH);          // (32, 64)
    flash_attn<<<fg, tb, FLASH_SMEM>>>(pq, pk, pv, pao);

    gemm_nt<<<gb, tb>>>(pao, Wo, out, nullptr, nullptr, 2);
}

// round 3
// speedup vs baseline: 1.4740x; 1.4740x over previous
#include <cuda_runtime.h>
#include <cuda_bf16.h>
#include <cstdint>
#include <cstddef>

// Problem constants
#define PB 4
#define PS 2048
#define PD 2048
#define PH 16
#define PDK 128
#define PM (PB*PS)          // 8192

// ---------------------------------------------------------------------------
// Scratch (device globals; no allocation allowed)
// ---------------------------------------------------------------------------
__device__ float g_q [PB*PH*PS*PDK];   // [B,H,S,DK] fp32
__device__ float g_k [PB*PH*PS*PDK];
__device__ float g_v [PB*PH*PS*PDK];
__device__ float g_ao[PM*PD];          // attention output [B,S,D] fp32

__device__ __nv_bfloat16 g_xhi [PM*PD], g_xlo [PM*PD];
__device__ __nv_bfloat16 g_aohi[PM*PD], g_aolo[PM*PD];
__device__ __nv_bfloat16 g_wqhi[PD*PD], g_wqlo[PD*PD];
__device__ __nv_bfloat16 g_wkhi[PD*PD], g_wklo[PD*PD];
__device__ __nv_bfloat16 g_wvhi[PD*PD], g_wvlo[PD*PD];
__device__ __nv_bfloat16 g_wohi[PD*PD], g_wolo[PD*PD];

// ---------------------------------------------------------------------------
// Helpers
// ---------------------------------------------------------------------------
__device__ __forceinline__ uint32_t smem_u32(const void* p) {
    uint32_t a;
    asm("{ .reg .u64 t; cvta.to.shared.u64 t, %1; cvt.u32.u64 %0, t; }"
        : "=r"(a) : "l"(p));
    return a;
}
#define CP_ASYNC16(dst, src) \
    asm volatile("cp.async.cg.shared.global [%0], [%1], 16;" :: "r"(dst), "l"(src) : "memory")
#define CP_COMMIT() asm volatile("cp.async.commit_group;" ::: "memory")
#define CP_WAIT1()  asm volatile("cp.async.wait_group 1;" ::: "memory")
#define CP_WAIT0()  asm volatile("cp.async.wait_group 0;" ::: "memory")

#define LDSM_X4(r0, r1, r2, r3, addr) \
    asm volatile("ldmatrix.sync.aligned.m8n8.x4.shared.b16 {%0,%1,%2,%3}, [%4];" \
                 : "=r"(r0), "=r"(r1), "=r"(r2), "=r"(r3) : "r"(addr))

#define MMA_BF16(c0, c1, c2, c3, a0, a1, a2, a3, b0, b1) \
    asm volatile("mma.sync.aligned.m16n8k16.row.col.f32.bf16.bf16.f32 " \
                 "{%0,%1,%2,%3}, {%4,%5,%6,%7}, {%8,%9}, {%0,%1,%2,%3};" \
                 : "+f"(c0), "+f"(c1), "+f"(c2), "+f"(c3) \
                 : "r"(a0), "r"(a1), "r"(a2), "r"(a3), "r"(b0), "r"(b1))

// ---------------------------------------------------------------------------
// Split fp32 -> bf16 hi + lo residual
// ---------------------------------------------------------------------------
__global__ void split_f32(const float4* __restrict__ in,
                          __nv_bfloat162* __restrict__ hi,
                          __nv_bfloat162* __restrict__ lo, int n4)
{
    int i = blockIdx.x * blockDim.x + threadIdx.x;
    if (i >= n4) return;
    float4 v = in[i];
    __nv_bfloat16 h0 = __float2bfloat16_rn(v.x);
    __nv_bfloat16 h1 = __float2bfloat16_rn(v.y);
    __nv_bfloat16 h2 = __float2bfloat16_rn(v.z);
    __nv_bfloat16 h3 = __float2bfloat16_rn(v.w);
    __nv_bfloat16 l0 = __float2bfloat16_rn(v.x - __bfloat162float(h0));
    __nv_bfloat16 l1 = __float2bfloat16_rn(v.y - __bfloat162float(h1));
    __nv_bfloat16 l2 = __float2bfloat16_rn(v.z - __bfloat162float(h2));
    __nv_bfloat16 l3 = __float2bfloat16_rn(v.w - __bfloat162float(h3));
    hi[2*i]   = __halves2bfloat162(h0, h1);
    hi[2*i+1] = __halves2bfloat162(h2, h3);
    lo[2*i]   = __halves2bfloat162(l0, l1);
    lo[2*i+1] = __halves2bfloat162(l2, l3);
}

// ---------------------------------------------------------------------------
// mma.sync bf16x3 NT GEMM: C[m,n] = sum_k A[m,k]*W[n,k], fp32 accum.
// M=8192, N=2048, K=2048. CTA 128x128, BK=32, 8 warps (4x2), warp tile 32x64.
// 3-stage cp.async pipeline. Smem rows padded to 40 bf16 (80B) -> conflict-free
// ldmatrix. 3 passes: Ahi*Bhi + Ahi*Blo + Alo*Bhi share one fragment load.
// mode 0: RoPE + [B,H,S,DK]; mode 1: [B,H,S,DK]; mode 2: row-major [M,N].
// ---------------------------------------------------------------------------
#define BK      32
#define NCHUNK  (PD/BK)             // 64
#define RPAD    40                  // smem row stride in bf16 (80 bytes)
#define TILE_B  (128*RPAD*2)        // 10240 bytes per 128x32 tile
#define STAGE_B (4*TILE_B)          // 40960
#define NSTAGE  3
#define GEMM_SMEM (NSTAGE*STAGE_B)  // 122880

__device__ __forceinline__ void load_stage(uint32_t st,
    const __nv_bfloat16* __restrict__ Ahi, const __nv_bfloat16* __restrict__ Alo,
    const __nv_bfloat16* __restrict__ Bhi, const __nv_bfloat16* __restrict__ Blo,
    int rowBlock, int colBlock, int k0, int tid)
{
    const int r = tid >> 2, s = tid & 3;          // 2 chunks per thread per tile
    const int r2 = r + 64;
    const uint32_t o1 = (uint32_t)(r * 80 + s * 16);
    const uint32_t o2 = (uint32_t)(r2 * 80 + s * 16);
    const size_t ga1 = (size_t)(rowBlock + r)  * PD + k0 + s*8;
    const size_t ga2 = (size_t)(rowBlock + r2) * PD + k0 + s*8;
    const size_t gb1 = (size_t)(colBlock + r)  * PD + k0 + s*8;
    const size_t gb2 = (size_t)(colBlock + r2) * PD + k0 + s*8;
    CP_ASYNC16(st + o1,              (const void*)(Ahi + ga1));
    CP_ASYNC16(st + o2,              (const void*)(Ahi + ga2));
    CP_ASYNC16(st + TILE_B + o1,     (const void*)(Alo + ga1));
    CP_ASYNC16(st + TILE_B + o2,     (const void*)(Alo + ga2));
    CP_ASYNC16(st + 2*TILE_B + o1,   (const void*)(Bhi + gb1));
    CP_ASYNC16(st + 2*TILE_B + o2,   (const void*)(Bhi + gb2));
    CP_ASYNC16(st + 3*TILE_B + o1,   (const void*)(Blo + gb1));
    CP_ASYNC16(st + 3*TILE_B + o2,   (const void*)(Blo + gb2));
}

__global__ __launch_bounds__(256, 1)
void gemm_mma(const __nv_bfloat16* __restrict__ Ahi, const __nv_bfloat16* __restrict__ Alo,
              const __nv_bfloat16* __restrict__ Bhi, const __nv_bfloat16* __restrict__ Blo,
              float* __restrict__ C, const float* __restrict__ cosp,
              const float* __restrict__ sinp, int mode)
{
    extern __shared__ char smem[];
    const uint32_t sb = smem_u32(smem);
    const int tid  = threadIdx.x;
    const int wid  = tid >> 5, lane = tid & 31;
    const int warpM = (wid & 3) * 32;      // 4 warps in M
    const int warpN = (wid >> 2) * 64;     // 2 warps in N
    const int rowBlock = blockIdx.y * 128;
    const int colBlock = blockIdx.x * 128;

    float acc[2][8][4];
#pragma unroll
    for (int i = 0; i < 2; ++i)
#pragma unroll
        for (int j = 0; j < 8; ++j)
#pragma unroll
            for (int q = 0; q < 4; ++q) acc[i][j][q] = 0.0f;

    // prologue: stages 0,1
    load_stage(sb,           Ahi, Alo, Bhi, Blo, rowBlock, colBlock, 0,  tid);
    CP_COMMIT();
    load_stage(sb + STAGE_B, Ahi, Alo, Bhi, Blo, rowBlock, colBlock, BK, tid);
    CP_COMMIT();

    // per-warp ldmatrix base offsets (within a tile)
    const uint32_t aRow = (uint32_t)(warpM + (lane & 15)) * 80 + (uint32_t)(lane >> 4) * 16;
    const uint32_t bRow = (uint32_t)(warpN + (lane & 15)) * 80 + (uint32_t)(lane >> 4) * 16;

    for (int c = 0; c < NCHUNK; ++c) {
        if (c == NCHUNK - 1) { CP_WAIT0(); } else { CP_WAIT1(); }
        __syncthreads();

        const uint32_t st = sb + (uint32_t)(c % NSTAGE) * STAGE_B;

        if (c + 2 < NCHUNK) {
            load_stage(sb + (uint32_t)((c + 2) % NSTAGE) * STAGE_B,
                       Ahi, Alo, Bhi, Blo, rowBlock, colBlock, (c + 2) * BK, tid);
            CP_COMMIT();
        }

#pragma unroll
        for (int ks = 0; ks < 2; ++ks) {
            const uint32_t ko = (uint32_t)ks * 32;
            // A fragments: hi and lo, 2 m-tiles each
            uint32_t ah[2][4], al[2][4];
#pragma unroll
            for (int mi = 0; mi < 2; ++mi) {
                LDSM_X4(ah[mi][0], ah[mi][1], ah[mi][2], ah[mi][3],
                        st + aRow + (uint32_t)mi*16*80 + ko);
                LDSM_X4(al[mi][0], al[mi][1], al[mi][2], al[mi][3],
                        st + TILE_B + aRow + (uint32_t)mi*16*80 + ko);
            }
            // B fragments: hi and lo, 4 n16-tiles each (8 n8-frags)
            uint32_t bh[4][4], bl[4][4];
#pragma unroll
            for (int ni = 0; ni < 4; ++ni) {
                LDSM_X4(bh[ni][0], bh[ni][1], bh[ni][2], bh[ni][3],
                        st + 2*TILE_B + bRow + (uint32_t)ni*16*80 + ko);
                LDSM_X4(bl[ni][0], bl[ni][1], bl[ni][2], bl[ni][3],
                        st + 3*TILE_B + bRow + (uint32_t)ni*16*80 + ko);
            }
            // n8 fragment j (0..7): regs {x[j>>1][(j&1)], x[j>>1][(j&1)+2]}
#pragma unroll
            for (int mi = 0; mi < 2; ++mi) {
#pragma unroll
                for (int j = 0; j < 8; ++j) {
                    const int t = j >> 1, u = j & 1;
                    // hi*hi
                    MMA_BF16(acc[mi][j][0], acc[mi][j][1], acc[mi][j][2], acc[mi][j][3],
                             ah[mi][0], ah[mi][1], ah[mi][2], ah[mi][3],
                             bh[t][u], bh[t][u+2]);
                    // hi*lo
                    MMA_BF16(acc[mi][j][0], acc[mi][j][1], acc[mi][j][2], acc[mi][j][3],
                             ah[mi][0], ah[mi][1], ah[mi][2], ah[mi][3],
                             bl[t][u], bl[t][u+2]);
                    // lo*hi
                    MMA_BF16(acc[mi][j][0], acc[mi][j][1], acc[mi][j][2], acc[mi][j][3],
                             al[mi][0], al[mi][1], al[mi][2], al[mi][3],
                             bh[t][u], bh[t][u+2]);
                }
            }
        }
        __syncthreads();
    }

    // ---------------- epilogue (register fragments) ----------------
    const int qlane = lane >> 2;          // 0..7
    const int nPair = (lane & 3) * 2;     // even col within n8 tile
    const int head  = colBlock >> 7;      // mode 0/1

#pragma unroll
    for (int mi = 0; mi < 2; ++mi) {
#pragma unroll
        for (int h = 0; h < 2; ++h) {
            const int m = rowBlock + warpM + mi*16 + h*8 + qlane;
            const int s = m & (PS - 1);
            const int b = m >> 11;
#pragma unroll
            for (int j = 0; j < 8; ++j) {
                float e0 = acc[mi][j][h*2];
                float e1 = acc[mi][j][h*2 + 1];
                const int nloc = warpN + j*8 + nPair;       // 0..127, even
                if (mode == 2) {
                    *(float2*)(C + (size_t)m*PD + colBlock + nloc) = make_float2(e0, e1);
                } else {
                    if (mode == 0) {
                        const float cc = cosp[s*64 + (nloc >> 1)];
                        const float sn = sinp[s*64 + (nloc >> 1)];
                        const float xe = e0, xo = e1;
                        e0 = xe*cc - xo*sn;
                        e1 = xo*cc + xe*sn;
                    }
                    float* dst = C + (((size_t)b*PH + head)*PS + s)*PDK + nloc;
                    *(float2*)dst = make_float2(e0, e1);
                }
            }
        }
    }
}

// ---------------------------------------------------------------------------
// Flash attention, fp32, causal (unchanged from R1 — proven)
// ---------------------------------------------------------------------------
#define FLASH_SMEM ((3*128*64 + 64*64) * 4)

__global__ __launch_bounds__(256, 2)
void flash_attn(const float* __restrict__ gq, const float* __restrict__ gk,
                const float* __restrict__ gv, float* __restrict__ gout)
{
    extern __shared__ float smf[];
    float* Qt = smf;
    float* Kt = smf + 128*64;
    float* Vs = smf + 2*128*64;
    float* Ps = smf + 3*128*64;

    const int tid = threadIdx.x;
    const int tx = tid & 15, ty = tid >> 4;
    const int qb = blockIdx.x;
    const int bh = blockIdx.y;

    const float* Qg = gq + ((size_t)bh*PS + qb*64) * PDK;
    const float* Kg = gk + (size_t)bh*PS*PDK;
    const float* Vg = gv + (size_t)bh*PS*PDK;

    const float scale = 0.08838834764831845f;

#pragma unroll
    for (int it = 0; it < 8; ++it) {
        const int id = tid + it*256;
        const int r = id & 63, kq = id >> 6;
        float4 v = *(const float4*)(Qg + r*PDK + kq*4);
        Qt[(kq*4+0)*64 + r] = v.x * scale;
        Qt[(kq*4+1)*64 + r] = v.y * scale;
        Qt[(kq*4+2)*64 + r] = v.z * scale;
        Qt[(kq*4+3)*64 + r] = v.w * scale;
    }

    float accO[4][8];
    float m_i[4], l_i[4];
#pragma unroll
    for (int i = 0; i < 4; ++i) {
        m_i[i] = -1e30f; l_i[i] = 0.0f;
#pragma unroll
        for (int c = 0; c < 8; ++c) accO[i][c] = 0.0f;
    }
    __syncthreads();

    for (int kb = 0; kb <= qb; ++kb) {
        const float* Kgb = Kg + (size_t)kb*64*PDK;
        const float* Vgb = Vg + (size_t)kb*64*PDK;
#pragma unroll
        for (int it = 0; it < 8; ++it) {
            const int id = tid + it*256;
            const int r = id & 63, kq = id >> 6;
            float4 v = *(const float4*)(Kgb + r*PDK + kq*4);
            Kt[(kq*4+0)*64 + r] = v.x;
            Kt[(kq*4+1)*64 + r] = v.y;
            Kt[(kq*4+2)*64 + r] = v.z;
            Kt[(kq*4+3)*64 + r] = v.w;
        }
#pragma unroll
        for (int it = 0; it < 8; ++it) {
            const int id = tid + it*256;
            const int r = id >> 5, cq = id & 31;
            *(float4*)(Vs + r*PDK + cq*4) = *(const float4*)(Vgb + r*PDK + cq*4);
        }
        __syncthreads();

        float sc[4][4];
#pragma unroll
        for (int i = 0; i < 4; ++i)
#pragma unroll
            for (int j = 0; j < 4; ++j) sc[i][j] = 0.0f;

#pragma unroll 4
        for (int k = 0; k < 128; ++k) {
            float4 qv = *(const float4*)(Qt + k*64 + ty*4);
            float4 kv = *(const float4*)(Kt + k*64 + tx*4);
            float qa[4] = {qv.x, qv.y, qv.z, qv.w};
            float ka[4] = {kv.x, kv.y, kv.z, kv.w};
#pragma unroll
            for (int i = 0; i < 4; ++i)
#pragma unroll
                for (int j = 0; j < 4; ++j)
                    sc[i][j] = fmaf(qa[i], ka[j], sc[i][j]);
        }

        if (kb == qb) {
#pragma unroll
            for (int i = 0; i < 4; ++i)
#pragma unroll
                for (int j = 0; j < 4; ++j)
                    if (tx*4 + j > ty*4 + i) sc[i][j] = -1e30f;
        }

#pragma unroll
        for (int i = 0; i < 4; ++i) {
            float bm = fmaxf(fmaxf(sc[i][0], sc[i][1]), fmaxf(sc[i][2], sc[i][3]));
#pragma unroll
            for (int off = 1; off < 16; off <<= 1)
                bm = fmaxf(bm, __shfl_xor_sync(0xffffffffu, bm, off));
            const float mn = fmaxf(m_i[i], bm);
            const float alpha = __expf(m_i[i] - mn);
            m_i[i] = mn;
            float p0 = __expf(sc[i][0] - mn);
            float p1 = __expf(sc[i][1] - mn);
            float p2 = __expf(sc[i][2] - mn);
            float p3 = __expf(sc[i][3] - mn);
            *(float4*)(Ps + (ty*4+i)*64 + tx*4) = make_float4(p0, p1, p2, p3);
            float rs = p0 + p1 + p2 + p3;
#pragma unroll
            for (int off = 1; off < 16; off <<= 1)
                rs += __shfl_xor_sync(0xffffffffu, rs, off);
            l_i[i] = l_i[i]*alpha + rs;
#pragma unroll
            for (int c = 0; c < 8; ++c) accO[i][c] *= alpha;
        }
        __syncthreads();

#pragma unroll 4
        for (int t = 0; t < 64; ++t) {
            float4 v0 = *(const float4*)(Vs + t*PDK + tx*4);
            float4 v1 = *(const float4*)(Vs + t*PDK + 64 + tx*4);
#pragma unroll
            for (int i = 0; i < 4; ++i) {
                const float p = Ps[(ty*4+i)*64 + t];
                accO[i][0] = fmaf(p, v0.x, accO[i][0]);
                accO[i][1] = fmaf(p, v0.y, accO[i][1]);
                accO[i][2] = fmaf(p, v0.z, accO[i][2]);
                accO[i][3] = fmaf(p, v0.w, accO[i][3]);
                accO[i][4] = fmaf(p, v1.x, accO[i][4]);
                accO[i][5] = fmaf(p, v1.y, accO[i][5]);
                accO[i][6] = fmaf(p, v1.z, accO[i][6]);
                accO[i][7] = fmaf(p, v1.w, accO[i][7]);
            }
        }
        __syncthreads();
    }

    const int b = bh >> 4, h = bh & 15;
#pragma unroll
    for (int i = 0; i < 4; ++i) {
        const float inv = 1.0f / l_i[i];
        const int sg = qb*64 + ty*4 + i;
        const size_t base = ((size_t)b*PS + sg)*PD + h*PDK;
        *(float4*)(gout + base + tx*4) =
            make_float4(accO[i][0]*inv, accO[i][1]*inv, accO[i][2]*inv, accO[i][3]*inv);
        *(float4*)(gout + base + 64 + tx*4) =
            make_float4(accO[i][4]*inv, accO[i][5]*inv, accO[i][6]*inv, accO[i][7]*inv);
    }
}

// ---------------------------------------------------------------------------
extern "C" void kernel_launch(void* const* d_in, const int* in_sizes, int n_in,
                              void* d_out, int out_size)
{
    (void)in_sizes; (void)n_in; (void)out_size;
    const float* x  = (const float*)d_in[0];
    const float* Wq = (const float*)d_in[1];
    const float* Wk = (const float*)d_in[2];
    const float* Wv = (const float*)d_in[3];
    const float* Wo = (const float*)d_in[4];
    const float* cs = (const float*)d_in[5];
    const float* sn = (const float*)d_in[6];
    float* out = (float*)d_out;

    float *pq, *pk, *pv, *pao;
    __nv_bfloat16 *xhi, *xlo, *aohi, *aolo;
    __nv_bfloat16 *wqh, *wql, *wkh, *wkl, *wvh, *wvl, *woh, *wol;
    cudaGetSymbolAddress((void**)&pq,   g_q);
    cudaGetSymbolAddress((void**)&pk,   g_k);
    cudaGetSymbolAddress((void**)&pv,   g_v);
    cudaGetSymbolAddress((void**)&pao,  g_ao);
    cudaGetSymbolAddress((void**)&xhi,  g_xhi);
    cudaGetSymbolAddress((void**)&xlo,  g_xlo);
    cudaGetSymbolAddress((void**)&aohi, g_aohi);
    cudaGetSymbolAddress((void**)&aolo, g_aolo);
    cudaGetSymbolAddress((void**)&wqh,  g_wqhi);
    cudaGetSymbolAddress((void**)&wql,  g_wqlo);
    cudaGetSymbolAddress((void**)&wkh,  g_wkhi);
    cudaGetSymbolAddress((void**)&wkl,  g_wklo);
    cudaGetSymbolAddress((void**)&wvh,  g_wvhi);
    cudaGetSymbolAddress((void**)&wvl,  g_wvlo);
    cudaGetSymbolAddress((void**)&woh,  g_wohi);
    cudaGetSymbolAddress((void**)&wol,  g_wolo);

    cudaFuncSetAttribute(gemm_mma, cudaFuncAttributeMaxDynamicSharedMemorySize, GEMM_SMEM);
    cudaFuncSetAttribute(flash_attn, cudaFuncAttributeMaxDynamicSharedMemorySize, FLASH_SMEM);

    const int TB = 256;
    {
        int n4 = PM*PD/4;
        split_f32<<<(n4 + TB - 1)/TB, TB>>>((const float4*)x, (__nv_bfloat162*)xhi,
                                            (__nv_bfloat162*)xlo, n4);
        int w4 = PD*PD/4;
        split_f32<<<(w4 + TB - 1)/TB, TB>>>((const float4*)Wq, (__nv_bfloat162*)wqh,
                                            (__nv_bfloat162*)wql, w4);
        split_f32<<<(w4 + TB - 1)/TB, TB>>>((const float4*)Wk, (__nv_bfloat162*)wkh,
                                            (__nv_bfloat162*)wkl, w4);
        split_f32<<<(w4 + TB - 1)/TB, TB>>>((const float4*)Wv, (__nv_bfloat162*)wvh,
                                            (__nv_bfloat162*)wvl, w4);
        split_f32<<<(w4 + TB - 1)/TB, TB>>>((const float4*)Wo, (__nv_bfloat162*)woh,
                                            (__nv_bfloat162*)wol, w4);
    }

    dim3 gb(PD/128, PM/128);   // (16, 64)
    const dim3 tb(256);
    gemm_mma<<<gb, tb, GEMM_SMEM>>>(xhi, xlo, wqh, wql, pq, cs, sn, 0);
    gemm_mma<<<gb, tb, GEMM_SMEM>>>(xhi, xlo, wkh, wkl, pk, cs, sn, 0);
    gemm_mma<<<gb, tb, GEMM_SMEM>>>(xhi, xlo, wvh, wvl, pv, cs, sn, 1);

    dim3 fg(PS/64, PB*PH);     // (32, 64)
    flash_attn<<<fg, tb, FLASH_SMEM>>>(pq, pk, pv, pao);

    {
        int n4 = PM*PD/4;
        split_f32<<<(n4 + TB - 1)/TB, TB>>>((const float4*)pao, (__nv_bfloat162*)aohi,
                                            (__nv_bfloat162*)aolo, n4);
    }
    gemm_mma<<<gb, tb, GEMM_SMEM>>>(aohi, aolo, woh, wol, out, nullptr, nullptr, 2);
}